// round 1
// baseline (speedup 1.0000x reference)
#include <cuda_runtime.h>
#include <cstdint>

#define DD 4096
#define LL 6
#define BLOCK 1024
// each thread owns one float4 = 4 columns; 1024 threads * 4 = 4096 = D

__global__ __launch_bounds__(BLOCK, 1)
void crossnet_fused_kernel(const float* __restrict__ x0g,
                           const float* __restrict__ wg,
                           const float* __restrict__ bg,
                           float* __restrict__ outg,
                           int B)
{
    extern __shared__ float smem[];
    float* bsh      = smem;                 // LL*DD floats (96 KB)
    float* partials = bsh + LL * DD;        // 2 * 32
    float* sums     = partials + 64;        // 2

    const int tid  = threadIdx.x;
    const int lane = tid & 31;
    const int wid  = tid >> 5;

    // ---- load b into shared (cooperative, coalesced float4) ----
    const float4* b4   = reinterpret_cast<const float4*>(bg);
    float4*       bsh4 = reinterpret_cast<float4*>(bsh);
    #pragma unroll
    for (int i = 0; i < (LL * DD / 4) / BLOCK; i++)
        bsh4[i * BLOCK + tid] = b4[i * BLOCK + tid];

    // ---- w for this thread's 4 columns, all layers, into registers ----
    const float4* w4 = reinterpret_cast<const float4*>(wg);
    float4 wr[LL];
    #pragma unroll
    for (int l = 0; l < LL; l++)
        wr[l] = w4[l * (DD / 4) + tid];

    __syncthreads();

    const float4* x04  = reinterpret_cast<const float4*>(x0g);
    float4*       out4 = reinterpret_cast<float4*>(outg);

    const int npairs = B >> 1;           // B is even (16384)
    const int stride = gridDim.x;

    int pair = blockIdx.x;

    // prefetch first pair
    float4 pA = make_float4(0.f, 0.f, 0.f, 0.f);
    float4 pB = pA;
    if (pair < npairs) {
        size_t rA = (size_t)(2 * pair)     * (DD / 4) + tid;
        size_t rB = (size_t)(2 * pair + 1) * (DD / 4) + tid;
        pA = x04[rA];
        pB = x04[rB];
    }

    for (; pair < npairs; pair += stride) {
        float4 x0A = pA, x0B = pB;
        float4 xA = x0A, xB = x0B;

        // prefetch next pair (overlaps with the 6-layer reduce chain)
        int np = pair + stride;
        if (np < npairs) {
            size_t rA = (size_t)(2 * np)     * (DD / 4) + tid;
            size_t rB = (size_t)(2 * np + 1) * (DD / 4) + tid;
            pA = x04[rA];
            pB = x04[rB];
        }

        #pragma unroll
        for (int l = 0; l < LL; l++) {
            const float4 w = wr[l];

            // per-thread partial dot for both rows
            float a = xA.x * w.x + xA.y * w.y + xA.z * w.z + xA.w * w.w;
            float c = xB.x * w.x + xB.y * w.y + xB.z * w.z + xB.w * w.w;

            // warp reduce (both rows interleaved to overlap shfl latency)
            #pragma unroll
            for (int o = 16; o > 0; o >>= 1) {
                a += __shfl_xor_sync(0xffffffffu, a, o);
                c += __shfl_xor_sync(0xffffffffu, c, o);
            }
            if (lane == 0) {
                partials[wid]      = a;
                partials[32 + wid] = c;
            }
            __syncthreads();

            // second-stage reduce: warp 0 -> row A, warp 1 -> row B
            if (wid < 2) {
                float v = partials[wid * 32 + lane];
                #pragma unroll
                for (int o = 16; o > 0; o >>= 1)
                    v += __shfl_xor_sync(0xffffffffu, v, o);
                if (lane == 0) sums[wid] = v;
            }
            __syncthreads();

            const float sA = sums[0];
            const float sB = sums[1];
            const float4 bv = bsh4[l * (DD / 4) + tid];

            // x = x0 * s + b + x   (same b for both rows)
            xA.x = fmaf(x0A.x, sA, bv.x + xA.x);
            xA.y = fmaf(x0A.y, sA, bv.y + xA.y);
            xA.z = fmaf(x0A.z, sA, bv.z + xA.z);
            xA.w = fmaf(x0A.w, sA, bv.w + xA.w);

            xB.x = fmaf(x0B.x, sB, bv.x + xB.x);
            xB.y = fmaf(x0B.y, sB, bv.y + xB.y);
            xB.z = fmaf(x0B.z, sB, bv.z + xB.z);
            xB.w = fmaf(x0B.w, sB, bv.w + xB.w);
        }

        size_t rA = (size_t)(2 * pair)     * (DD / 4) + tid;
        size_t rB = (size_t)(2 * pair + 1) * (DD / 4) + tid;
        out4[rA] = xA;
        out4[rB] = xB;
    }
}

extern "C" void kernel_launch(void* const* d_in, const int* in_sizes, int n_in,
                              void* d_out, int out_size)
{
    const float* x0 = (const float*)d_in[0];   // inputs [B, D] f32
    const float* w  = (const float*)d_in[1];   // w [L, D, 1]  f32
    const float* b  = (const float*)d_in[2];   // b [L, D]     f32
    float* out      = (float*)d_out;           // [B, D]       f32

    const int B = in_sizes[0] / DD;

    // dynamic smem: b cache + reduction scratch
    const int smem_bytes = (LL * DD + 64 + 2) * (int)sizeof(float);

    static int sm_count = 0;
    if (sm_count == 0) {
        cudaDeviceGetAttribute(&sm_count, cudaDevAttrMultiProcessorCount, 0);
        cudaFuncSetAttribute(crossnet_fused_kernel,
                             cudaFuncAttributeMaxDynamicSharedMemorySize,
                             smem_bytes);
        if (sm_count <= 0) sm_count = 148;
    }

    crossnet_fused_kernel<<<sm_count, BLOCK, smem_bytes>>>(x0, w, b, out, B);
}

// round 2
// speedup vs baseline: 1.5738x; 1.5738x over previous
#include <cuda_runtime.h>

#define DD 4096
#define LL 6
#define BLOCK 1024
// 1024 threads * float4 = 4096 = D; each thread owns 4 columns of every row.

__global__ __launch_bounds__(BLOCK, 1)
void crossnet_dcn_kernel(const float* __restrict__ x0g,
                         const float* __restrict__ wg,
                         const float* __restrict__ bg,
                         float* __restrict__ outg,
                         int B)
{
    __shared__ float s_part[32][13];   // per-warp partials, stride 13 = conflict-free
    __shared__ float s_u[12];          // reduced u for 2 rows x 6 layers
    __shared__ float s_e[8];           // e_l scalars (row-independent)

    const int tid  = threadIdx.x;
    const int lane = tid & 31;
    const int wid  = tid >> 5;

    const float4* w4 = reinterpret_cast<const float4*>(wg);
    const float4* b4 = reinterpret_cast<const float4*>(bg);
    const float4* x4 = reinterpret_cast<const float4*>(x0g);
    float4*       o4 = reinterpret_cast<float4*>(outg);

    // ---- w for this thread's 4 columns, all layers (24 regs) ----
    float4 wr[LL];
#pragma unroll
    for (int l = 0; l < LL; l++) wr[l] = w4[l * (DD / 4) + tid];

    // ---- precompute d_L (vector, in regs) and e_l (scalars, in smem) ----
    // d_l = sum_{j<l} b_j ; e_l = d_l . w_l ; d_L = sum of all b_j
    float4 dl = make_float4(0.f, 0.f, 0.f, 0.f);
    float ep[LL];
#pragma unroll
    for (int l = 0; l < LL; l++) {
        ep[l] = dl.x * wr[l].x + dl.y * wr[l].y + dl.z * wr[l].z + dl.w * wr[l].w;
        float4 bv = b4[l * (DD / 4) + tid];
        dl.x += bv.x; dl.y += bv.y; dl.z += bv.z; dl.w += bv.w;
    }
#pragma unroll
    for (int o = 16; o > 0; o >>= 1)
#pragma unroll
        for (int l = 0; l < LL; l++) ep[l] += __shfl_xor_sync(0xffffffffu, ep[l], o);
    if (lane == 0)
#pragma unroll
        for (int l = 0; l < LL; l++) s_part[wid][l] = ep[l];
    __syncthreads();
    if (wid < LL) {
        float v = s_part[lane][wid];
#pragma unroll
        for (int o = 16; o > 0; o >>= 1) v += __shfl_xor_sync(0xffffffffu, v, o);
        if (lane == 0) s_e[wid] = v;
    }
    __syncthreads();

    // ---- main loop: 2 rows per iteration, one reduction round total ----
    const int npairs = B >> 1;
    const int stride = gridDim.x;

    int pair = blockIdx.x;
    float4 pA = make_float4(0.f, 0.f, 0.f, 0.f);
    float4 pB = pA;
    if (pair < npairs) {
        pA = __ldcs(&x4[(size_t)(2 * pair)     * (DD / 4) + tid]);
        pB = __ldcs(&x4[(size_t)(2 * pair + 1) * (DD / 4) + tid]);
    }

    for (; pair < npairs; pair += stride) {
        const float4 x0A = pA;
        const float4 x0B = pB;

        // prefetch next pair (overlaps reduction + epilogue)
        int np = pair + stride;
        if (np < npairs) {
            pA = __ldcs(&x4[(size_t)(2 * np)     * (DD / 4) + tid]);
            pB = __ldcs(&x4[(size_t)(2 * np + 1) * (DD / 4) + tid]);
        }

        // --- u_l partials for row A, reduce, park in smem ---
        {
            float p[LL];
#pragma unroll
            for (int l = 0; l < LL; l++) {
                p[l] = x0A.x * wr[l].x;
                p[l] = fmaf(x0A.y, wr[l].y, p[l]);
                p[l] = fmaf(x0A.z, wr[l].z, p[l]);
                p[l] = fmaf(x0A.w, wr[l].w, p[l]);
            }
#pragma unroll
            for (int o = 16; o > 0; o >>= 1)
#pragma unroll
                for (int l = 0; l < LL; l++) p[l] += __shfl_xor_sync(0xffffffffu, p[l], o);
            if (lane == 0)
#pragma unroll
                for (int l = 0; l < LL; l++) s_part[wid][l] = p[l];
        }
        // --- row B ---
        {
            float p[LL];
#pragma unroll
            for (int l = 0; l < LL; l++) {
                p[l] = x0B.x * wr[l].x;
                p[l] = fmaf(x0B.y, wr[l].y, p[l]);
                p[l] = fmaf(x0B.z, wr[l].z, p[l]);
                p[l] = fmaf(x0B.w, wr[l].w, p[l]);
            }
#pragma unroll
            for (int o = 16; o > 0; o >>= 1)
#pragma unroll
                for (int l = 0; l < LL; l++) p[l] += __shfl_xor_sync(0xffffffffu, p[l], o);
            if (lane == 0)
#pragma unroll
                for (int l = 0; l < LL; l++) s_part[wid][LL + l] = p[l];
        }
        __syncthreads();

        // --- second stage: warps 0..11 each reduce one (row,l) over 32 warp-partials ---
        if (wid < 2 * LL) {
            float v = s_part[lane][wid];
#pragma unroll
            for (int o = 16; o > 0; o >>= 1) v += __shfl_xor_sync(0xffffffffu, v, o);
            if (lane == 0) s_u[wid] = v;
        }
        __syncthreads();

        // --- scalar recurrence + epilogue ---
        float cA = 1.f, cB = 1.f;
#pragma unroll
        for (int l = 0; l < LL; l++) {
            const float e = s_e[l];
            cA = fmaf(cA, s_u[l],      cA + e);   // c = c*(1+u) + e
            cB = fmaf(cB, s_u[LL + l], cB + e);
        }

        float4 rA, rB;
        rA.x = fmaf(x0A.x, cA, dl.x);
        rA.y = fmaf(x0A.y, cA, dl.y);
        rA.z = fmaf(x0A.z, cA, dl.z);
        rA.w = fmaf(x0A.w, cA, dl.w);
        rB.x = fmaf(x0B.x, cB, dl.x);
        rB.y = fmaf(x0B.y, cB, dl.y);
        rB.z = fmaf(x0B.z, cB, dl.z);
        rB.w = fmaf(x0B.w, cB, dl.w);

        __stcs(&o4[(size_t)(2 * pair)     * (DD / 4) + tid], rA);
        __stcs(&o4[(size_t)(2 * pair + 1) * (DD / 4) + tid], rB);
    }
}

extern "C" void kernel_launch(void* const* d_in, const int* in_sizes, int n_in,
                              void* d_out, int out_size)
{
    const float* x0 = (const float*)d_in[0];   // inputs [B, D] f32
    const float* w  = (const float*)d_in[1];   // w [L, D, 1]  f32
    const float* b  = (const float*)d_in[2];   // b [L, D]     f32
    float* out      = (float*)d_out;           // [B, D]       f32

    const int B = in_sizes[0] / DD;

    static int sm_count = 0;
    if (sm_count == 0) {
        cudaDeviceGetAttribute(&sm_count, cudaDevAttrMultiProcessorCount, 0);
        if (sm_count <= 0) sm_count = 148;
    }

    crossnet_dcn_kernel<<<sm_count, BLOCK>>>(x0, w, b, out, B);
}

// round 3
// speedup vs baseline: 1.8783x; 1.1934x over previous
#include <cuda_runtime.h>

#define DD 4096
#define LL 6
#define BLOCK 1024
// 1024 threads * float4 = 4096 = D; each thread owns 4 columns of every row.

__global__ __launch_bounds__(BLOCK, 1)
void crossnet_dcn_kernel(const float* __restrict__ x0g,
                         const float* __restrict__ wg,
                         const float* __restrict__ bg,
                         float* __restrict__ outg,
                         int B)
{
    __shared__ float s_part[32][13];   // per-warp partials, stride 13 = conflict-free
    __shared__ float s_c[2];           // broadcast cA, cB

    const int tid  = threadIdx.x;
    const int lane = tid & 31;
    const int wid  = tid >> 5;

    const float4* w4 = reinterpret_cast<const float4*>(wg);
    const float4* b4 = reinterpret_cast<const float4*>(bg);
    const float4* x4 = reinterpret_cast<const float4*>(x0g);
    float4*       o4 = reinterpret_cast<float4*>(outg);

    // ---- w for this thread's 4 columns, all layers (24 regs) ----
    float4 wr[LL];
#pragma unroll
    for (int l = 0; l < LL; l++) wr[l] = w4[l * (DD / 4) + tid];

    // ---- preamble: d_L (vector, regs) and e_l = d_l . w_l (scalars) ----
    float4 dl = make_float4(0.f, 0.f, 0.f, 0.f);
    {
        float ep[LL];
#pragma unroll
        for (int l = 0; l < LL; l++) {
            ep[l] = dl.x * wr[l].x + dl.y * wr[l].y + dl.z * wr[l].z + dl.w * wr[l].w;
            float4 bv = b4[l * (DD / 4) + tid];
            dl.x += bv.x; dl.y += bv.y; dl.z += bv.z; dl.w += bv.w;
        }
#pragma unroll
        for (int o = 16; o > 0; o >>= 1)
#pragma unroll
            for (int l = 0; l < LL; l++) ep[l] += __shfl_xor_sync(0xffffffffu, ep[l], o);
        if (lane == 0)
#pragma unroll
            for (int l = 0; l < LL; l++) s_part[wid][l] = ep[l];
    }
    __syncthreads();

    float eR[LL];                      // valid (used) in warp 0 only
    if (wid == 0) {
#pragma unroll
        for (int l = 0; l < LL; l++) {
            float t = s_part[lane][l];
#pragma unroll
            for (int o = 16; o > 0; o >>= 1) t += __shfl_xor_sync(0xffffffffu, t, o);
            eR[l] = t;
        }
    }
    __syncthreads();

    // ---- main loop: 2 rows per iteration ----
    const int npairs = B >> 1;
    const int stride = gridDim.x;

    int pair = blockIdx.x;
    float4 pA = make_float4(0.f, 0.f, 0.f, 0.f);
    float4 pB = pA;
    if (pair < npairs) {
        pA = __ldcs(&x4[(size_t)(2 * pair)     * (DD / 4) + tid]);
        pB = __ldcs(&x4[(size_t)(2 * pair + 1) * (DD / 4) + tid]);
    }

    for (; pair < npairs; pair += stride) {
        const float4 x0A = pA;
        const float4 x0B = pB;

        // prefetch next pair (overlaps reduce + epilogue)
        int np = pair + stride;
        if (np < npairs) {
            pA = __ldcs(&x4[(size_t)(2 * np)     * (DD / 4) + tid]);
            pB = __ldcs(&x4[(size_t)(2 * np + 1) * (DD / 4) + tid]);
        }

        // per-thread partial dots: v[l] = rowA layer l, v[6+l] = rowB layer l
        float v[12];
#pragma unroll
        for (int l = 0; l < LL; l++) {
            float a = x0A.x * wr[l].x;
            a = fmaf(x0A.y, wr[l].y, a);
            a = fmaf(x0A.z, wr[l].z, a);
            a = fmaf(x0A.w, wr[l].w, a);
            v[l] = a;
            float c = x0B.x * wr[l].x;
            c = fmaf(x0B.y, wr[l].y, c);
            c = fmaf(x0B.z, wr[l].z, c);
            c = fmaf(x0B.w, wr[l].w, c);
            v[LL + l] = c;
        }

        // transposed multi-value warp reduce: 16 logical slots (12 real),
        // round dists 16,8,4,2 then final xor-1. Value i lands on lanes {2i,2i+1}.
        {
            bool hi = (lane & 16) != 0;
#pragma unroll
            for (int j = 0; j < 8; j++) {
                float vh   = (j + 8 < 12) ? v[j + 8] : 0.f;
                float send = hi ? v[j] : vh;
                float keep = hi ? vh : v[j];
                v[j] = keep + __shfl_xor_sync(0xffffffffu, send, 16);
            }
        }
#pragma unroll
        for (int r = 1; r < 4; r++) {
            const int dist = 16 >> r;
            const int nv   = 8 >> r;
            bool hi = (lane & dist) != 0;
#pragma unroll
            for (int j = 0; j < nv; j++) {
                float send = hi ? v[j] : v[j + nv];
                float keep = hi ? v[j + nv] : v[j];
                v[j] = keep + __shfl_xor_sync(0xffffffffu, send, dist);
            }
        }
        v[0] += __shfl_xor_sync(0xffffffffu, v[0], 1);

        // lane 2*idx (even lanes, idx<12) stores its value: ONE predicated STS
        if ((lane & 1) == 0 && (lane >> 1) < 12)
            s_part[wid][lane >> 1] = v[0];

        __syncthreads();

        // stage-2: warp 0 reduces 32 warp-partials per value, runs recurrence
        if (wid == 0) {
            float r2[12];
#pragma unroll
            for (int j = 0; j < 12; j++) r2[j] = s_part[lane][j];
            {
                bool hi = (lane & 16) != 0;
#pragma unroll
                for (int j = 0; j < 8; j++) {
                    float vh   = (j + 8 < 12) ? r2[j + 8] : 0.f;
                    float send = hi ? r2[j] : vh;
                    float keep = hi ? vh : r2[j];
                    r2[j] = keep + __shfl_xor_sync(0xffffffffu, send, 16);
                }
            }
#pragma unroll
            for (int r = 1; r < 4; r++) {
                const int dist = 16 >> r;
                const int nv   = 8 >> r;
                bool hi = (lane & dist) != 0;
#pragma unroll
                for (int j = 0; j < nv; j++) {
                    float send = hi ? r2[j] : r2[j + nv];
                    float keep = hi ? r2[j + nv] : r2[j];
                    r2[j] = keep + __shfl_xor_sync(0xffffffffu, send, dist);
                }
            }
            r2[0] += __shfl_xor_sync(0xffffffffu, r2[0], 1);
            // value idx lives on lane 2*idx: uA_l at 2l, uB_l at 12+2l

            float cA = 1.f, cB = 1.f;
#pragma unroll
            for (int l = 0; l < LL; l++) {
                float uA = __shfl_sync(0xffffffffu, r2[0], 2 * l);
                float uB = __shfl_sync(0xffffffffu, r2[0], 12 + 2 * l);
                cA = fmaf(cA, uA, cA + eR[l]);   // c = c*(1+u) + e
                cB = fmaf(cB, uB, cB + eR[l]);
            }
            if (lane == 0) { s_c[0] = cA; s_c[1] = cB; }
        }
        __syncthreads();

        const float cA = s_c[0];
        const float cB = s_c[1];

        float4 rA, rB;
        rA.x = fmaf(x0A.x, cA, dl.x);
        rA.y = fmaf(x0A.y, cA, dl.y);
        rA.z = fmaf(x0A.z, cA, dl.z);
        rA.w = fmaf(x0A.w, cA, dl.w);
        rB.x = fmaf(x0B.x, cB, dl.x);
        rB.y = fmaf(x0B.y, cB, dl.y);
        rB.z = fmaf(x0B.z, cB, dl.z);
        rB.w = fmaf(x0B.w, cB, dl.w);

        __stcs(&o4[(size_t)(2 * pair)     * (DD / 4) + tid], rA);
        __stcs(&o4[(size_t)(2 * pair + 1) * (DD / 4) + tid], rB);
    }
}

extern "C" void kernel_launch(void* const* d_in, const int* in_sizes, int n_in,
                              void* d_out, int out_size)
{
    const float* x0 = (const float*)d_in[0];   // inputs [B, D] f32
    const float* w  = (const float*)d_in[1];   // w [L, D, 1]  f32
    const float* b  = (const float*)d_in[2];   // b [L, D]     f32
    float* out      = (float*)d_out;           // [B, D]       f32

    const int B = in_sizes[0] / DD;

    static int sm_count = 0;
    if (sm_count == 0) {
        cudaDeviceGetAttribute(&sm_count, cudaDevAttrMultiProcessorCount, 0);
        if (sm_count <= 0) sm_count = 148;
    }

    crossnet_dcn_kernel<<<sm_count, BLOCK>>>(x0, w, b, out, B);
}